// round 10
// baseline (speedup 1.0000x reference)
#include <cuda_runtime.h>
#include <cuda_fp16.h>
#include <cstdint>
#include <cstddef>

#define N_NODES 8192
#define DIN     512
#define DOUT    256
#define ALPHA   0.2f
#define NEG_INF -9e15f
#define L2E     1.4426950408889634f

// ---------------- scratch (device globals; no allocations allowed) ----------
__device__ __half g_Whh[(size_t)N_NODES * DOUT];   // 4 MB fp16 row-major (k4 B)
__device__ float  g_wa[2][DIN];                    // W @ a halves (k0 -> k2)
__device__ float g_src[N_NODES];
__device__ float g_dst[N_NODES];
__device__ float g_rmax[N_NODES];
__device__ float g_rsum[N_NODES];

// ---------------- helpers ----------------------------------------------------
__device__ __forceinline__ uint32_t smem_u32(const void* p) {
    uint32_t a;
    asm("{ .reg .u64 t; cvta.to.shared.u64 t, %1; cvt.u32.u64 %0, t; }"
        : "=r"(a) : "l"(p));
    return a;
}
__device__ __forceinline__ void ldmx4(uint32_t* r, uint32_t addr) {
    asm volatile("ldmatrix.sync.aligned.m8n8.x4.shared.b16 {%0,%1,%2,%3}, [%4];"
                 : "=r"(r[0]), "=r"(r[1]), "=r"(r[2]), "=r"(r[3]) : "r"(addr));
}
__device__ __forceinline__ void ldmx4t(uint32_t* r, uint32_t addr) {
    asm volatile("ldmatrix.sync.aligned.m8n8.x4.trans.shared.b16 {%0,%1,%2,%3}, [%4];"
                 : "=r"(r[0]), "=r"(r[1]), "=r"(r[2]), "=r"(r[3]) : "r"(addr));
}
__device__ __forceinline__ void mma16816(float* c, const uint32_t* a,
                                         uint32_t b0, uint32_t b1) {
    asm volatile(
        "mma.sync.aligned.m16n8k16.row.col.f32.f16.f16.f32 "
        "{%0,%1,%2,%3}, {%4,%5,%6,%7}, {%8,%9}, {%0,%1,%2,%3};\n"
        : "+f"(c[0]), "+f"(c[1]), "+f"(c[2]), "+f"(c[3])
        : "r"(a[0]), "r"(a[1]), "r"(a[2]), "r"(a[3]), "r"(b0), "r"(b1));
}
__device__ __forceinline__ void cp_async16(uint32_t smem_addr, const void* gptr) {
    asm volatile("cp.async.cg.shared.global [%0], [%1], 16;\n"
                 :: "r"(smem_addr), "l"(gptr));
}
__device__ __forceinline__ void cp_commit() {
    asm volatile("cp.async.commit_group;\n" ::: "memory");
}
template <int N>
__device__ __forceinline__ void cp_wait() {
    asm volatile("cp.async.wait_group %0;\n" :: "n"(N) : "memory");
}

// ---------------- K0: wa[p][k] = sum_d W[k][d] * a[p*256+d]  (tiny) ----------
__global__ void __launch_bounds__(256) k0_wa(const float* __restrict__ W,
                                             const float* __restrict__ a) {
    int lane = threadIdx.x & 31, w = threadIdx.x >> 5;
    int id = blockIdx.x * 8 + w;          // 0..1023
    int proj = id >> 9, k = id & 511;
    float s = 0.f;
    #pragma unroll
    for (int d = lane; d < DOUT; d += 32)
        s += W[(size_t)k * DOUT + d] * a[proj * DOUT + d];
    #pragma unroll
    for (int o = 16; o > 0; o >>= 1) s += __shfl_xor_sync(0xffffffffu, s, o);
    if (lane == 0) g_wa[proj][k] = s;
}

// ---------------- K1: Whh = fp16( X @ W )  via ldmatrix + HMMA ---------------
// Grid (128, 4): 64-row x 64-col tiles, K-tiles of 32. Block 256 (2mi x 4nj).
__global__ void __launch_bounds__(256) k1_gemm(const float* __restrict__ X,
                                               const float* __restrict__ W) {
    __shared__ __align__(16) char xs[5120];   // 64 rows x 80B (fp16, stride 80)
    __shared__ __align__(16) char ws[4096];   // 32 k-rows x 128B, swizzle c^(r&7)
    int t    = threadIdx.x;
    int lane = t & 31, w = t >> 5;
    int mi = w & 1, nj = w >> 1;
    int m0 = blockIdx.x * 64, n0 = blockIdx.y * 64;

    float acc[2][2][4];
    #pragma unroll
    for (int i = 0; i < 2; i++)
        #pragma unroll
        for (int j = 0; j < 2; j++)
            #pragma unroll
            for (int q = 0; q < 4; q++) acc[i][j][q] = 0.f;

    int xrow = t >> 2, xk8 = (t & 3) * 8;
    int wr = t >> 3, c1 = t & 7;
    uint32_t pbase = smem_u32(xs), wbase = smem_u32(ws);

    int rowM = (lane & 7) + ((lane >> 3) & 1) * 8;
    uint32_t aAddr = pbase + (mi * 32 + rowM) * 80 + (lane >> 4) * 16;
    int cs = (nj * 2 + (lane >> 4)) ^ (lane & 7);
    uint32_t bAddr = wbase + rowM * 128 + cs * 16;

    for (int k0 = 0; k0 < DIN; k0 += 32) {
        __syncthreads();
        {   // X tile 64x32: fp32 -> fp16, stride-80 rows
            float4 x0 = *(const float4*)&X[(size_t)(m0 + xrow) * DIN + k0 + xk8];
            float4 x1 = *(const float4*)&X[(size_t)(m0 + xrow) * DIN + k0 + xk8 + 4];
            __half2 h0 = __floats2half2_rn(x0.x, x0.y);
            __half2 h1 = __floats2half2_rn(x0.z, x0.w);
            __half2 h2 = __floats2half2_rn(x1.x, x1.y);
            __half2 h3 = __floats2half2_rn(x1.z, x1.w);
            uint4 v;
            v.x = *(uint32_t*)&h0; v.y = *(uint32_t*)&h1;
            v.z = *(uint32_t*)&h2; v.w = *(uint32_t*)&h3;
            *(uint4*)&xs[xrow * 80 + (t & 3) * 16] = v;
        }
        {   // W tile 32x64: fp32 -> fp16, 128B rows, chunk swizzle
            float4 w0 = *(const float4*)&W[(size_t)(k0 + wr) * DOUT + n0 + c1 * 8];
            float4 w1 = *(const float4*)&W[(size_t)(k0 + wr) * DOUT + n0 + c1 * 8 + 4];
            __half2 h0 = __floats2half2_rn(w0.x, w0.y);
            __half2 h1 = __floats2half2_rn(w0.z, w0.w);
            __half2 h2 = __floats2half2_rn(w1.x, w1.y);
            __half2 h3 = __floats2half2_rn(w1.z, w1.w);
            uint4 v;
            v.x = *(uint32_t*)&h0; v.y = *(uint32_t*)&h1;
            v.z = *(uint32_t*)&h2; v.w = *(uint32_t*)&h3;
            *(uint4*)&ws[wr * 128 + ((c1 ^ (wr & 7)) * 16)] = v;
        }
        __syncthreads();
        #pragma unroll
        for (int ks = 0; ks < 2; ks++) {
            uint32_t b[4];
            ldmx4t(b, bAddr + ks * 2048);
            #pragma unroll
            for (int itile = 0; itile < 2; itile++) {
                uint32_t a[4];
                ldmx4(a, aAddr + itile * 1280 + ks * 32);
                mma16816(acc[itile][0], a, b[0], b[1]);
                mma16816(acc[itile][1], a, b[2], b[3]);
            }
        }
    }

    #pragma unroll
    for (int itile = 0; itile < 2; itile++) {
        int r0 = m0 + mi * 32 + itile * 16 + (lane >> 2);
        #pragma unroll
        for (int nb = 0; nb < 2; nb++) {
            int c = n0 + nj * 16 + nb * 8 + (lane & 3) * 2;
            __half2 lo = __floats2half2_rn(acc[itile][nb][0], acc[itile][nb][1]);
            __half2 hi = __floats2half2_rn(acc[itile][nb][2], acc[itile][nb][3]);
            *(__half2*)&g_Whh[(size_t)r0 * DOUT + c]       = lo;
            *(__half2*)&g_Whh[(size_t)(r0 + 8) * DOUT + c] = hi;
        }
    }
}

// ---------------- K2: src/dst = X @ wa  (exact fp32 logits) ------------------
__global__ void __launch_bounds__(256) k2_srcdst(const float* __restrict__ X) {
    int lane = threadIdx.x & 31, w = threadIdx.x >> 5;
    int i = blockIdx.x * 8 + w;
    float s1 = 0.f, s2 = 0.f;
    #pragma unroll
    for (int c = lane; c < DIN; c += 32) {
        float x = X[(size_t)i * DIN + c];
        s1 += x * g_wa[0][c];
        s2 += x * g_wa[1][c];
    }
    #pragma unroll
    for (int o = 16; o > 0; o >>= 1) {
        s1 += __shfl_xor_sync(0xffffffffu, s1, o);
        s2 += __shfl_xor_sync(0xffffffffu, s2, o);
    }
    if (lane == 0) { g_src[i] = s1; g_dst[i] = s2; }
}

// ---------------- K3: per-row max and sum(exp(e - m)) ------------------------
__global__ void __launch_bounds__(256) k3_rowstats(const int* __restrict__ adj) {
    int i = blockIdx.x;
    int t = threadIdx.x;
    int lane = t & 31, w = t >> 5;
    __shared__ float red[8];
    __shared__ float bcast;

    float si = g_src[i];
    float ev[32];
    float mx = NEG_INF;
    #pragma unroll
    for (int s = 0; s < 8; s++) {
        int j = (s * 256 + t) * 4;
        int4   a4 = *(const int4*)&adj[(size_t)i * N_NODES + j];
        float4 d4 = *(const float4*)&g_dst[j];
        float xs[4] = {si + d4.x, si + d4.y, si + d4.z, si + d4.w};
        int   am[4] = {a4.x, a4.y, a4.z, a4.w};
        #pragma unroll
        for (int c = 0; c < 4; c++) {
            float x = xs[c];
            float e = fmaxf(x, ALPHA * x);
            e = (am[c] > 0) ? e : NEG_INF;
            ev[s * 4 + c] = e;
            mx = fmaxf(mx, e);
        }
    }
    #pragma unroll
    for (int o = 16; o > 0; o >>= 1) mx = fmaxf(mx, __shfl_xor_sync(0xffffffffu, mx, o));
    if (lane == 0) red[w] = mx;
    __syncthreads();
    if (t == 0) {
        float m2 = red[0];
        #pragma unroll
        for (int q = 1; q < 8; q++) m2 = fmaxf(m2, red[q]);
        bcast = m2;
    }
    __syncthreads();
    float bm = bcast;

    float sum = 0.f;
    #pragma unroll
    for (int q = 0; q < 32; q++) sum += __expf(ev[q] - bm);
    #pragma unroll
    for (int o = 16; o > 0; o >>= 1) sum += __shfl_xor_sync(0xffffffffu, sum, o);
    __syncthreads();
    if (lane == 0) red[w] = sum;
    __syncthreads();
    if (t == 0) {
        float s2 = 0.f;
        #pragma unroll
        for (int q = 0; q < 8; q++) s2 += red[q];
        g_rmax[i] = bm;
        g_rsum[i] = s2;
    }
}

// ---------------- K4: h' = softmax(P) @ Wh, fp16 mma + ldmatrix --------------
// Grid (2, 256): x = 128-col half, y = 32-row tile -> 512 CTAs (occupancy).
// Block 256 = 8 warps, nj = w over 16-col slices. Warp tile 32x16.
// Builders: threads t<128 (R9's proven uint4/stride-80 pattern, rows 0..31).
// Wh: 32k x 256B rows, chunk swizzle c^(r&7). Double-buffered, 1 barrier/tile.
#define KT   32
#define NIT  (N_NODES / KT)

__global__ void __launch_bounds__(256, 3) k4_attn(const int* __restrict__ adj,
                                                  float* __restrict__ out) {
    __shared__ __align__(16) char whsm[2][8192];   // [stage][32 k-rows][256B]
    __shared__ __align__(16) char psm [2][2560];   // [stage][32 rows][80B]
    __shared__ float src_s[32], m2_s[32], linv_s[32];

    int t    = threadIdx.x;
    int lane = t & 31, w = t >> 5;
    int nj = w;              // 16-col slice
    int J0 = blockIdx.x * 128;
    int I0 = blockIdx.y * 32;

    if (t < 32) {
        src_s[t]  = g_src[I0 + t];
        m2_s[t]   = g_rmax[I0 + t] * L2E;
        linv_s[t] = 1.0f / g_rsum[I0 + t];
    }

    float acc[2][2][4];
    #pragma unroll
    for (int i = 0; i < 2; i++)
        #pragma unroll
        for (int j = 0; j < 2; j++)
            #pragma unroll
            for (int q = 0; q < 4; q++) acc[i][j][q] = 0.f;

    // ---- builder mapping (t<128): row rb = t>>2, k-chunk kc8 = (t&3)*8 ----
    int rb  = (t & 127) >> 2;
    int kc8 = (t & 3) * 8;
    const int* adjrow = adj + (size_t)(I0 + rb) * N_NODES + kc8;
    bool is_builder = (t < 128);

    // ---- Wh cp.async mapping: row wr = t>>3, chunks c1, c1+8 (swizzled) ----
    int wr = t >> 3, c1 = t & 7;
    uint32_t wh_dst = smem_u32(&whsm[0][0]) + wr * 256 + ((c1 ^ (wr & 7)) * 16);
    const __half* wh_src = &g_Whh[(size_t)wr * DOUT + J0 + c1 * 8];

    // ---- ldmatrix lane address components ----
    uint32_t pbase  = smem_u32(&psm[0][0]);
    uint32_t whbase = smem_u32(&whsm[0][0]);
    int rowM = (lane & 7) + ((lane >> 3) & 1) * 8;
    uint32_t aAddr0 = pbase + rowM * 80 + (lane >> 4) * 16;
    int cs = (nj * 2 + (lane >> 4)) ^ (lane & 7);
    uint32_t bAddr0 = whbase + rowM * 256 + cs * 16;

    // ---- prologue ----
    cp_async16(wh_dst, wh_src);
    cp_async16(wh_dst + 128, wh_src + 64);
    cp_commit();
    int4 aj0, aj1;
    if (is_builder) {
        aj0 = *(const int4*)&adjrow[0];
        aj1 = *(const int4*)&adjrow[4];
    }

    __syncthreads();    // stats visible
    float sv = 0.f, mt2 = 0.f;
    if (is_builder) { sv = src_s[rb]; mt2 = m2_s[rb]; }

    // build P[0]
    if (is_builder) {
        float4 d0 = *(const float4*)&g_dst[kc8];
        float4 d1 = *(const float4*)&g_dst[kc8 + 4];
        float xs[8] = {sv + d0.x, sv + d0.y, sv + d0.z, sv + d0.w,
                       sv + d1.x, sv + d1.y, sv + d1.z, sv + d1.w};
        int   am[8] = {aj0.x, aj0.y, aj0.z, aj0.w, aj1.x, aj1.y, aj1.z, aj1.w};
        float p[8];
        #pragma unroll
        for (int c = 0; c < 8; c++) {
            float x = xs[c];
            float e = fmaxf(x, ALPHA * x);
            e = (am[c] > 0) ? e : NEG_INF;
            p[c] = exp2f(fmaf(e, L2E, -mt2));
        }
        __half2 h0 = __floats2half2_rn(p[0], p[1]);
        __half2 h1 = __floats2half2_rn(p[2], p[3]);
        __half2 h2 = __floats2half2_rn(p[4], p[5]);
        __half2 h3 = __floats2half2_rn(p[6], p[7]);
        uint4 v;
        v.x = *(uint32_t*)&h0; v.y = *(uint32_t*)&h1;
        v.z = *(uint32_t*)&h2; v.w = *(uint32_t*)&h3;
        *(uint4*)&psm[0][rb * 80 + (t & 3) * 16] = v;
        // prefetch adj tile 1
        aj0 = *(const int4*)&adjrow[KT];
        aj1 = *(const int4*)&adjrow[KT + 4];
    }

    for (int it = 0; it < NIT; ++it) {
        int cur = it & 1;
        int nxt = cur ^ 1;
        bool more = (it + 1 < NIT);

        cp_wait<0>();
        __syncthreads();   // publishes stage cur; retires all reads of nxt

        if (more) {
            int kn = (it + 1) * KT;
            cp_async16(wh_dst + nxt * 8192, wh_src + (size_t)kn * DOUT);
            cp_async16(wh_dst + nxt * 8192 + 128, wh_src + (size_t)kn * DOUT + 64);
            cp_commit();

            if (is_builder) {
                float4 d0 = *(const float4*)&g_dst[kn + kc8];
                float4 d1 = *(const float4*)&g_dst[kn + kc8 + 4];
                float xs[8] = {sv + d0.x, sv + d0.y, sv + d0.z, sv + d0.w,
                               sv + d1.x, sv + d1.y, sv + d1.z, sv + d1.w};
                int   am[8] = {aj0.x, aj0.y, aj0.z, aj0.w,
                               aj1.x, aj1.y, aj1.z, aj1.w};
                float p[8];
                #pragma unroll
                for (int c = 0; c < 8; c++) {
                    float x = xs[c];
                    float e = fmaxf(x, ALPHA * x);
                    e = (am[c] > 0) ? e : NEG_INF;
                    p[c] = exp2f(fmaf(e, L2E, -mt2));
                }
                __half2 h0 = __floats2half2_rn(p[0], p[1]);
                __half2 h1 = __floats2half2_rn(p[2], p[3]);
                __half2 h2 = __floats2half2_rn(p[4], p[5]);
                __half2 h3 = __floats2half2_rn(p[6], p[7]);
                uint4 v;
                v.x = *(uint32_t*)&h0; v.y = *(uint32_t*)&h1;
                v.z = *(uint32_t*)&h2; v.w = *(uint32_t*)&h3;
                *(uint4*)&psm[nxt][rb * 80 + (t & 3) * 16] = v;

                if (it + 2 < NIT) {
                    const int* ab = adjrow + (it + 2) * KT;
                    aj0 = *(const int4*)&ab[0];
                    aj1 = *(const int4*)&ab[4];
                }
            }
        }

        // ---- MMA on stage cur: warp tile 32 rows x 16 cols ----
        {
            uint32_t aA = aAddr0 + cur * 2560;
            uint32_t bA = bAddr0 + cur * 8192;
            #pragma unroll
            for (int ks = 0; ks < 2; ks++) {
                uint32_t b[4];
                ldmx4t(b, bA + ks * 4096);
                #pragma unroll
                for (int itile = 0; itile < 2; itile++) {
                    uint32_t a[4];
                    ldmx4(a, aA + itile * 1280 + ks * 32);
                    mma16816(acc[itile][0], a, b[0], b[1]);
                    mma16816(acc[itile][1], a, b[2], b[3]);
                }
            }
        }
    }

    // ---- epilogue: /rowsum, ELU, store ----
    #pragma unroll
    for (int itile = 0; itile < 2; itile++) {
        int r0 = itile * 16 + (lane >> 2);
        float l0 = linv_s[r0], l1 = linv_s[r0 + 8];
        #pragma unroll
        for (int nb = 0; nb < 2; nb++) {
            int c = J0 + nj * 16 + nb * 8 + (lane & 3) * 2;
            float v0 = acc[itile][nb][0] * l0;
            float v1 = acc[itile][nb][1] * l0;
            float v2 = acc[itile][nb][2] * l1;
            float v3 = acc[itile][nb][3] * l1;
            float2 lo, hi;
            lo.x = (v0 > 0.f) ? v0 : expm1f(v0);
            lo.y = (v1 > 0.f) ? v1 : expm1f(v1);
            hi.x = (v2 > 0.f) ? v2 : expm1f(v2);
            hi.y = (v3 > 0.f) ? v3 : expm1f(v3);
            *(float2*)&out[(size_t)(I0 + r0)     * DOUT + c] = lo;
            *(float2*)&out[(size_t)(I0 + r0 + 8) * DOUT + c] = hi;
        }
    }
}

// ---------------- launch ------------------------------------------------------
extern "C" void kernel_launch(void* const* d_in, const int* in_sizes, int n_in,
                              void* d_out, int out_size) {
    const float* X   = (const float*)d_in[0];   // features [8192,512]
    const int*   adj = (const int*)  d_in[1];   // adj      [8192,8192]
    const float* W   = (const float*)d_in[2];   // W        [512,256]
    const float* a   = (const float*)d_in[3];   // a        [512,1]
    float* out = (float*)d_out;                 // [8192,256]

    k0_wa      <<<128, 256>>>(W, a);
    k1_gemm    <<<dim3(N_NODES / 64, DOUT / 64), 256>>>(X, W);
    k2_srcdst  <<<N_NODES / 8, 256>>>(X);
    k3_rowstats<<<N_NODES, 256>>>(adj);
    k4_attn    <<<dim3(DOUT / 128, N_NODES / 32), 256>>>(adj, out);
}

// round 13
// speedup vs baseline: 1.5320x; 1.5320x over previous
#include <cuda_runtime.h>
#include <cuda_fp16.h>
#include <cstdint>
#include <cstddef>

#define N_NODES 8192
#define DIN     512
#define DOUT    256
#define ALPHA   0.2f
#define NEG_INF -9e15f
#define L2E     1.4426950408889634f

// ---------------- scratch (device globals; no allocations allowed) ----------
__device__ __half g_Whh[(size_t)N_NODES * DOUT];   // 4 MB fp16 row-major (k4 B)
__device__ float  g_wa[2][DIN];                    // W @ a halves (k0 -> k2)
__device__ float g_src[N_NODES];
__device__ float g_dst[N_NODES];
__device__ float g_rmax[N_NODES];
__device__ float g_rsum[N_NODES];

// ---------------- helpers ----------------------------------------------------
__device__ __forceinline__ uint32_t smem_u32(const void* p) {
    uint32_t a;
    asm("{ .reg .u64 t; cvta.to.shared.u64 t, %1; cvt.u32.u64 %0, t; }"
        : "=r"(a) : "l"(p));
    return a;
}
__device__ __forceinline__ void ldmx4(uint32_t* r, uint32_t addr) {
    asm volatile("ldmatrix.sync.aligned.m8n8.x4.shared.b16 {%0,%1,%2,%3}, [%4];"
                 : "=r"(r[0]), "=r"(r[1]), "=r"(r[2]), "=r"(r[3]) : "r"(addr));
}
__device__ __forceinline__ void ldmx4t(uint32_t* r, uint32_t addr) {
    asm volatile("ldmatrix.sync.aligned.m8n8.x4.trans.shared.b16 {%0,%1,%2,%3}, [%4];"
                 : "=r"(r[0]), "=r"(r[1]), "=r"(r[2]), "=r"(r[3]) : "r"(addr));
}
__device__ __forceinline__ void mma16816(float* c, const uint32_t* a,
                                         uint32_t b0, uint32_t b1) {
    asm volatile(
        "mma.sync.aligned.m16n8k16.row.col.f32.f16.f16.f32 "
        "{%0,%1,%2,%3}, {%4,%5,%6,%7}, {%8,%9}, {%0,%1,%2,%3};\n"
        : "+f"(c[0]), "+f"(c[1]), "+f"(c[2]), "+f"(c[3])
        : "r"(a[0]), "r"(a[1]), "r"(a[2]), "r"(a[3]), "r"(b0), "r"(b1));
}
__device__ __forceinline__ void cp_async16(uint32_t smem_addr, const void* gptr) {
    asm volatile("cp.async.cg.shared.global [%0], [%1], 16;\n"
                 :: "r"(smem_addr), "l"(gptr));
}
__device__ __forceinline__ void cp_commit() {
    asm volatile("cp.async.commit_group;\n" ::: "memory");
}
template <int N>
__device__ __forceinline__ void cp_wait() {
    asm volatile("cp.async.wait_group %0;\n" :: "n"(N) : "memory");
}

// ---------------- K0: wa[p][k] = sum_d W[k][d] * a[p*256+d]  (tiny) ----------
__global__ void __launch_bounds__(256) k0_wa(const float* __restrict__ W,
                                             const float* __restrict__ a) {
    int lane = threadIdx.x & 31, w = threadIdx.x >> 5;
    int id = blockIdx.x * 8 + w;          // 0..1023
    int proj = id >> 9, k = id & 511;
    float s = 0.f;
    #pragma unroll
    for (int d = lane; d < DOUT; d += 32)
        s += W[(size_t)k * DOUT + d] * a[proj * DOUT + d];
    #pragma unroll
    for (int o = 16; o > 0; o >>= 1) s += __shfl_xor_sync(0xffffffffu, s, o);
    if (lane == 0) g_wa[proj][k] = s;
}

// ---------------- K1: Whh = fp16( X @ W )  via ldmatrix + HMMA ---------------
// Grid (128, 4): 64-row x 64-col tiles, K-tiles of 32. Block 256 (2mi x 4nj).
__global__ void __launch_bounds__(256) k1_gemm(const float* __restrict__ X,
                                               const float* __restrict__ W) {
    __shared__ __align__(16) char xs[5120];   // 64 rows x 80B (fp16, stride 80)
    __shared__ __align__(16) char ws[4096];   // 32 k-rows x 128B, swizzle c^(r&7)
    int t    = threadIdx.x;
    int lane = t & 31, w = t >> 5;
    int mi = w & 1, nj = w >> 1;
    int m0 = blockIdx.x * 64, n0 = blockIdx.y * 64;

    float acc[2][2][4];
    #pragma unroll
    for (int i = 0; i < 2; i++)
        #pragma unroll
        for (int j = 0; j < 2; j++)
            #pragma unroll
            for (int q = 0; q < 4; q++) acc[i][j][q] = 0.f;

    int xrow = t >> 2, xk8 = (t & 3) * 8;
    int wr = t >> 3, c1 = t & 7;
    uint32_t pbase = smem_u32(xs), wbase = smem_u32(ws);

    int rowM = (lane & 7) + ((lane >> 3) & 1) * 8;
    uint32_t aAddr = pbase + (mi * 32 + rowM) * 80 + (lane >> 4) * 16;
    int cs = (nj * 2 + (lane >> 4)) ^ (lane & 7);
    uint32_t bAddr = wbase + rowM * 128 + cs * 16;

    for (int k0 = 0; k0 < DIN; k0 += 32) {
        __syncthreads();
        {   // X tile 64x32: fp32 -> fp16, stride-80 rows
            float4 x0 = *(const float4*)&X[(size_t)(m0 + xrow) * DIN + k0 + xk8];
            float4 x1 = *(const float4*)&X[(size_t)(m0 + xrow) * DIN + k0 + xk8 + 4];
            __half2 h0 = __floats2half2_rn(x0.x, x0.y);
            __half2 h1 = __floats2half2_rn(x0.z, x0.w);
            __half2 h2 = __floats2half2_rn(x1.x, x1.y);
            __half2 h3 = __floats2half2_rn(x1.z, x1.w);
            uint4 v;
            v.x = *(uint32_t*)&h0; v.y = *(uint32_t*)&h1;
            v.z = *(uint32_t*)&h2; v.w = *(uint32_t*)&h3;
            *(uint4*)&xs[xrow * 80 + (t & 3) * 16] = v;
        }
        {   // W tile 32x64: fp32 -> fp16, 128B rows, chunk swizzle
            float4 w0 = *(const float4*)&W[(size_t)(k0 + wr) * DOUT + n0 + c1 * 8];
            float4 w1 = *(const float4*)&W[(size_t)(k0 + wr) * DOUT + n0 + c1 * 8 + 4];
            __half2 h0 = __floats2half2_rn(w0.x, w0.y);
            __half2 h1 = __floats2half2_rn(w0.z, w0.w);
            __half2 h2 = __floats2half2_rn(w1.x, w1.y);
            __half2 h3 = __floats2half2_rn(w1.z, w1.w);
            uint4 v;
            v.x = *(uint32_t*)&h0; v.y = *(uint32_t*)&h1;
            v.z = *(uint32_t*)&h2; v.w = *(uint32_t*)&h3;
            *(uint4*)&ws[wr * 128 + ((c1 ^ (wr & 7)) * 16)] = v;
        }
        __syncthreads();
        #pragma unroll
        for (int ks = 0; ks < 2; ks++) {
            uint32_t b[4];
            ldmx4t(b, bAddr + ks * 2048);
            #pragma unroll
            for (int itile = 0; itile < 2; itile++) {
                uint32_t a[4];
                ldmx4(a, aAddr + itile * 1280 + ks * 32);
                mma16816(acc[itile][0], a, b[0], b[1]);
                mma16816(acc[itile][1], a, b[2], b[3]);
            }
        }
    }

    #pragma unroll
    for (int itile = 0; itile < 2; itile++) {
        int r0 = m0 + mi * 32 + itile * 16 + (lane >> 2);
        #pragma unroll
        for (int nb = 0; nb < 2; nb++) {
            int c = n0 + nj * 16 + nb * 8 + (lane & 3) * 2;
            __half2 lo = __floats2half2_rn(acc[itile][nb][0], acc[itile][nb][1]);
            __half2 hi = __floats2half2_rn(acc[itile][nb][2], acc[itile][nb][3]);
            *(__half2*)&g_Whh[(size_t)r0 * DOUT + c]       = lo;
            *(__half2*)&g_Whh[(size_t)(r0 + 8) * DOUT + c] = hi;
        }
    }
}

// ---------------- K2: src/dst = X @ wa  (exact fp32 logits) ------------------
__global__ void __launch_bounds__(256) k2_srcdst(const float* __restrict__ X) {
    int lane = threadIdx.x & 31, w = threadIdx.x >> 5;
    int i = blockIdx.x * 8 + w;
    float s1 = 0.f, s2 = 0.f;
    #pragma unroll
    for (int c = lane; c < DIN; c += 32) {
        float x = X[(size_t)i * DIN + c];
        s1 += x * g_wa[0][c];
        s2 += x * g_wa[1][c];
    }
    #pragma unroll
    for (int o = 16; o > 0; o >>= 1) {
        s1 += __shfl_xor_sync(0xffffffffu, s1, o);
        s2 += __shfl_xor_sync(0xffffffffu, s2, o);
    }
    if (lane == 0) { g_src[i] = s1; g_dst[i] = s2; }
}

// ---------------- K3: per-row max and sum(exp(e - m)) ------------------------
__global__ void __launch_bounds__(256) k3_rowstats(const int* __restrict__ adj) {
    int i = blockIdx.x;
    int t = threadIdx.x;
    int lane = t & 31, w = t >> 5;
    __shared__ float red[8];
    __shared__ float bcast;

    float si = g_src[i];
    float ev[32];
    float mx = NEG_INF;
    #pragma unroll
    for (int s = 0; s < 8; s++) {
        int j = (s * 256 + t) * 4;
        int4   a4 = *(const int4*)&adj[(size_t)i * N_NODES + j];
        float4 d4 = *(const float4*)&g_dst[j];
        float xs[4] = {si + d4.x, si + d4.y, si + d4.z, si + d4.w};
        int   am[4] = {a4.x, a4.y, a4.z, a4.w};
        #pragma unroll
        for (int c = 0; c < 4; c++) {
            float x = xs[c];
            float e = fmaxf(x, ALPHA * x);
            e = (am[c] > 0) ? e : NEG_INF;
            ev[s * 4 + c] = e;
            mx = fmaxf(mx, e);
        }
    }
    #pragma unroll
    for (int o = 16; o > 0; o >>= 1) mx = fmaxf(mx, __shfl_xor_sync(0xffffffffu, mx, o));
    if (lane == 0) red[w] = mx;
    __syncthreads();
    if (t == 0) {
        float m2 = red[0];
        #pragma unroll
        for (int q = 1; q < 8; q++) m2 = fmaxf(m2, red[q]);
        bcast = m2;
    }
    __syncthreads();
    float bm = bcast;

    float sum = 0.f;
    #pragma unroll
    for (int q = 0; q < 32; q++) sum += __expf(ev[q] - bm);
    #pragma unroll
    for (int o = 16; o > 0; o >>= 1) sum += __shfl_xor_sync(0xffffffffu, sum, o);
    __syncthreads();
    if (lane == 0) red[w] = sum;
    __syncthreads();
    if (t == 0) {
        float s2 = 0.f;
        #pragma unroll
        for (int q = 0; q < 8; q++) s2 += red[q];
        g_rmax[i] = bm;
        g_rsum[i] = s2;
    }
}

// ---------------- K4: h' = softmax(P) @ Wh, fp16 mma + ldmatrix --------------
// R9's proven best shape. Grid (2, 128): x = 128-col half, y = 64-row tile.
// Block 256 = 8 warps (mi = w&1 over 32-row halves, nj = w>>1 over 32-col
// quarters). Warp tile 32x32. K-tile 32 = 2 x m16n8k16 steps. P: 64x32 fp16,
// row stride 80B. Wh: 32x128 fp16, 256B rows, chunk swizzle c^(r&7).
// Double-buffered, one barrier per tile.
#define KT   32
#define NIT  (N_NODES / KT)

__global__ void __launch_bounds__(256, 2) k4_attn(const int* __restrict__ adj,
                                                  float* __restrict__ out) {
    __shared__ __align__(16) char whsm[2][8192];   // [stage][32 k-rows][256B]
    __shared__ __align__(16) char psm [2][5120];   // [stage][64 rows][80B]
    __shared__ float src_s[64], m2_s[64], linv_s[64];

    int t    = threadIdx.x;
    int lane = t & 31, w = t >> 5;
    int mi = w & 1;          // 32-row half
    int nj = w >> 1;         // 32-col quarter
    int J0 = blockIdx.x * 128;
    int I0 = blockIdx.y * 64;

    if (t < 64) {
        src_s[t]  = g_src[I0 + t];
        m2_s[t]   = g_rmax[I0 + t] * L2E;
        linv_s[t] = 1.0f / g_rsum[I0 + t];
    }

    float acc[2][4][4];
    #pragma unroll
    for (int i = 0; i < 2; i++)
        #pragma unroll
        for (int j = 0; j < 4; j++)
            #pragma unroll
            for (int q = 0; q < 4; q++) acc[i][j][q] = 0.f;

    // ---- builder mapping: row rb = t>>2, k-chunk kc8 = (t&3)*8 ----
    int rb  = t >> 2;
    int kc8 = (t & 3) * 8;
    const int* adjrow = adj + (size_t)(I0 + rb) * N_NODES + kc8;

    // ---- Wh cp.async mapping: row wr = t>>3, chunks c1, c1+8 (swizzled) -----
    int wr = t >> 3, c1 = t & 7;
    uint32_t wh_dst = smem_u32(&whsm[0][0]) + wr * 256 + ((c1 ^ (wr & 7)) * 16);
    const __half* wh_src = &g_Whh[(size_t)wr * DOUT + J0 + c1 * 8];

    // ---- ldmatrix lane address components ----
    uint32_t pbase  = smem_u32(&psm[0][0]);
    uint32_t whbase = smem_u32(&whsm[0][0]);
    int rowM = (lane & 7) + ((lane >> 3) & 1) * 8;       // 0..15
    uint32_t aAddr0 = pbase + (mi * 32 + rowM) * 80 + (lane >> 4) * 16;
    int cs0 = (nj * 4 + 0 + (lane >> 4)) ^ (lane & 7);
    int cs1 = (nj * 4 + 2 + (lane >> 4)) ^ (lane & 7);
    uint32_t bAddr0 = whbase + rowM * 256 + cs0 * 16;
    uint32_t bAddr1 = whbase + rowM * 256 + cs1 * 16;

    // ---- prologue ----
    cp_async16(wh_dst, wh_src);
    cp_async16(wh_dst + 128, wh_src + 64);
    cp_commit();
    int4 aj0 = *(const int4*)&adjrow[0];
    int4 aj1 = *(const int4*)&adjrow[4];

    __syncthreads();    // stats visible
    float sv  = src_s[rb];
    float mt2 = m2_s[rb];

    // build P[0]
    {
        float4 d0 = *(const float4*)&g_dst[kc8];
        float4 d1 = *(const float4*)&g_dst[kc8 + 4];
        float xs[8] = {sv + d0.x, sv + d0.y, sv + d0.z, sv + d0.w,
                       sv + d1.x, sv + d1.y, sv + d1.z, sv + d1.w};
        int   am[8] = {aj0.x, aj0.y, aj0.z, aj0.w, aj1.x, aj1.y, aj1.z, aj1.w};
        float p[8];
        #pragma unroll
        for (int c = 0; c < 8; c++) {
            float x = xs[c];
            float e = fmaxf(x, ALPHA * x);
            e = (am[c] > 0) ? e : NEG_INF;
            p[c] = exp2f(fmaf(e, L2E, -mt2));
        }
        __half2 h0 = __floats2half2_rn(p[0], p[1]);
        __half2 h1 = __floats2half2_rn(p[2], p[3]);
        __half2 h2 = __floats2half2_rn(p[4], p[5]);
        __half2 h3 = __floats2half2_rn(p[6], p[7]);
        uint4 v;
        v.x = *(uint32_t*)&h0; v.y = *(uint32_t*)&h1;
        v.z = *(uint32_t*)&h2; v.w = *(uint32_t*)&h3;
        *(uint4*)&psm[0][rb * 80 + (t & 3) * 16] = v;
    }
    // prefetch adj tile 1
    aj0 = *(const int4*)&adjrow[KT];
    aj1 = *(const int4*)&adjrow[KT + 4];

    for (int it = 0; it < NIT; ++it) {
        int cur = it & 1;
        int nxt = cur ^ 1;
        bool more = (it + 1 < NIT);

        cp_wait<0>();
        __syncthreads();   // publishes stage cur; retires all reads of nxt

        if (more) {
            int kn = (it + 1) * KT;
            // Wh[nxt]
            cp_async16(wh_dst + nxt * 8192, wh_src + (size_t)kn * DOUT);
            cp_async16(wh_dst + nxt * 8192 + 128, wh_src + (size_t)kn * DOUT + 64);
            cp_commit();

            // build P[nxt] (tile it+1)
            {
                float4 d0 = *(const float4*)&g_dst[kn + kc8];
                float4 d1 = *(const float4*)&g_dst[kn + kc8 + 4];
                float xs[8] = {sv + d0.x, sv + d0.y, sv + d0.z, sv + d0.w,
                               sv + d1.x, sv + d1.y, sv + d1.z, sv + d1.w};
                int   am[8] = {aj0.x, aj0.y, aj0.z, aj0.w,
                               aj1.x, aj1.y, aj1.z, aj1.w};
                float p[8];
                #pragma unroll
                for (int c = 0; c < 8; c++) {
                    float x = xs[c];
                    float e = fmaxf(x, ALPHA * x);
                    e = (am[c] > 0) ? e : NEG_INF;
                    p[c] = exp2f(fmaf(e, L2E, -mt2));
                }
                __half2 h0 = __floats2half2_rn(p[0], p[1]);
                __half2 h1 = __floats2half2_rn(p[2], p[3]);
                __half2 h2 = __floats2half2_rn(p[4], p[5]);
                __half2 h3 = __floats2half2_rn(p[6], p[7]);
                uint4 v;
                v.x = *(uint32_t*)&h0; v.y = *(uint32_t*)&h1;
                v.z = *(uint32_t*)&h2; v.w = *(uint32_t*)&h3;
                *(uint4*)&psm[nxt][rb * 80 + (t & 3) * 16] = v;
            }

            // prefetch adj for tile it+2
            if (it + 2 < NIT) {
                const int* ab = adjrow + (it + 2) * KT;
                aj0 = *(const int4*)&ab[0];
                aj1 = *(const int4*)&ab[4];
            }
        }

        // ---- MMA on stage cur: warp tile 32 rows x 32 cols ----
        {
            uint32_t aA = aAddr0 + cur * 5120;
            uint32_t bA0 = bAddr0 + cur * 8192;
            uint32_t bA1 = bAddr1 + cur * 8192;
            #pragma unroll
            for (int ks = 0; ks < 2; ks++) {
                uint32_t b0[4], b1[4];
                ldmx4t(b0, bA0 + ks * 4096);   // cols nj*32+0..15, k 16
                ldmx4t(b1, bA1 + ks * 4096);   // cols nj*32+16..31
                #pragma unroll
                for (int itile = 0; itile < 2; itile++) {
                    uint32_t a[4];
                    ldmx4(a, aA + itile * 1280 + ks * 32);
                    mma16816(acc[itile][0], a, b0[0], b0[1]);
                    mma16816(acc[itile][1], a, b0[2], b0[3]);
                    mma16816(acc[itile][2], a, b1[0], b1[1]);
                    mma16816(acc[itile][3], a, b1[2], b1[3]);
                }
            }
        }
    }

    // ---- epilogue: /rowsum, ELU, store ----
    #pragma unroll
    for (int itile = 0; itile < 2; itile++) {
        int r0 = mi * 32 + itile * 16 + (lane >> 2);
        float l0 = linv_s[r0], l1 = linv_s[r0 + 8];
        #pragma unroll
        for (int nb = 0; nb < 4; nb++) {
            int c = J0 + nj * 32 + nb * 8 + (lane & 3) * 2;
            float v0 = acc[itile][nb][0] * l0;
            float v1 = acc[itile][nb][1] * l0;
            float v2 = acc[itile][nb][2] * l1;
            float v3 = acc[itile][nb][3] * l1;
            float2 lo, hi;
            lo.x = (v0 > 0.f) ? v0 : expm1f(v0);
            lo.y = (v1 > 0.f) ? v1 : expm1f(v1);
            hi.x = (v2 > 0.f) ? v2 : expm1f(v2);
            hi.y = (v3 > 0.f) ? v3 : expm1f(v3);
            *(float2*)&out[(size_t)(I0 + r0)     * DOUT + c] = lo;
            *(float2*)&out[(size_t)(I0 + r0 + 8) * DOUT + c] = hi;
        }
    }
}

// ---------------- launch ------------------------------------------------------
extern "C" void kernel_launch(void* const* d_in, const int* in_sizes, int n_in,
                              void* d_out, int out_size) {
    const float* X   = (const float*)d_in[0];   // features [8192,512]
    const int*   adj = (const int*)  d_in[1];   // adj      [8192,8192]
    const float* W   = (const float*)d_in[2];   // W        [512,256]
    const float* a   = (const float*)d_in[3];   // a        [512,1]
    float* out = (float*)d_out;                 // [8192,256]

    k0_wa      <<<128, 256>>>(W, a);
    k1_gemm    <<<dim3(N_NODES / 64, DOUT / 64), 256>>>(X, W);
    k2_srcdst  <<<N_NODES / 8, 256>>>(X);
    k3_rowstats<<<N_NODES, 256>>>(adj);
    k4_attn    <<<dim3(DOUT / 128, N_NODES / 64), 256>>>(adj, out);
}

// round 14
// speedup vs baseline: 1.7329x; 1.1311x over previous
#include <cuda_runtime.h>
#include <cuda_fp16.h>
#include <cstdint>
#include <cstddef>

#define N_NODES 8192
#define DIN     512
#define DOUT    256
#define ALPHA   0.2f
#define NEG_INF -9e15f
#define L2E     1.4426950408889634f

// ---------------- scratch (device globals; no allocations allowed) ----------
__device__ __half g_Whh[(size_t)N_NODES * DOUT];   // 4 MB fp16 row-major (k4 B)
__device__ float  g_wa[2][DIN];                    // W @ a halves (k0 -> k2)
__device__ float g_src[N_NODES];
__device__ float g_dst[N_NODES];
__device__ float g_dmax;                           // max_j dst[j]

// ---------------- helpers ----------------------------------------------------
__device__ __forceinline__ uint32_t smem_u32(const void* p) {
    uint32_t a;
    asm("{ .reg .u64 t; cvta.to.shared.u64 t, %1; cvt.u32.u64 %0, t; }"
        : "=r"(a) : "l"(p));
    return a;
}
__device__ __forceinline__ void ldmx4(uint32_t* r, uint32_t addr) {
    asm volatile("ldmatrix.sync.aligned.m8n8.x4.shared.b16 {%0,%1,%2,%3}, [%4];"
                 : "=r"(r[0]), "=r"(r[1]), "=r"(r[2]), "=r"(r[3]) : "r"(addr));
}
__device__ __forceinline__ void ldmx4t(uint32_t* r, uint32_t addr) {
    asm volatile("ldmatrix.sync.aligned.m8n8.x4.trans.shared.b16 {%0,%1,%2,%3}, [%4];"
                 : "=r"(r[0]), "=r"(r[1]), "=r"(r[2]), "=r"(r[3]) : "r"(addr));
}
__device__ __forceinline__ void mma16816(float* c, const uint32_t* a,
                                         uint32_t b0, uint32_t b1) {
    asm volatile(
        "mma.sync.aligned.m16n8k16.row.col.f32.f16.f16.f32 "
        "{%0,%1,%2,%3}, {%4,%5,%6,%7}, {%8,%9}, {%0,%1,%2,%3};\n"
        : "+f"(c[0]), "+f"(c[1]), "+f"(c[2]), "+f"(c[3])
        : "r"(a[0]), "r"(a[1]), "r"(a[2]), "r"(a[3]), "r"(b0), "r"(b1));
}
__device__ __forceinline__ void cp_async16(uint32_t smem_addr, const void* gptr) {
    asm volatile("cp.async.cg.shared.global [%0], [%1], 16;\n"
                 :: "r"(smem_addr), "l"(gptr));
}
__device__ __forceinline__ void cp_commit() {
    asm volatile("cp.async.commit_group;\n" ::: "memory");
}
template <int N>
__device__ __forceinline__ void cp_wait() {
    asm volatile("cp.async.wait_group %0;\n" :: "n"(N) : "memory");
}

// ---------------- K0: wa[p][k] = sum_d W[k][d] * a[p*256+d]  (tiny) ----------
__global__ void __launch_bounds__(256) k0_wa(const float* __restrict__ W,
                                             const float* __restrict__ a) {
    int lane = threadIdx.x & 31, w = threadIdx.x >> 5;
    int id = blockIdx.x * 8 + w;          // 0..1023
    int proj = id >> 9, k = id & 511;
    float s = 0.f;
    #pragma unroll
    for (int d = lane; d < DOUT; d += 32)
        s += W[(size_t)k * DOUT + d] * a[proj * DOUT + d];
    #pragma unroll
    for (int o = 16; o > 0; o >>= 1) s += __shfl_xor_sync(0xffffffffu, s, o);
    if (lane == 0) g_wa[proj][k] = s;
}

// ---------------- K1: Whh = fp16( X @ W )  via ldmatrix + HMMA ---------------
__global__ void __launch_bounds__(256) k1_gemm(const float* __restrict__ X,
                                               const float* __restrict__ W) {
    __shared__ __align__(16) char xs[5120];   // 64 rows x 80B (fp16, stride 80)
    __shared__ __align__(16) char ws[4096];   // 32 k-rows x 128B, swizzle c^(r&7)
    int t    = threadIdx.x;
    int lane = t & 31, w = t >> 5;
    int mi = w & 1, nj = w >> 1;
    int m0 = blockIdx.x * 64, n0 = blockIdx.y * 64;

    float acc[2][2][4];
    #pragma unroll
    for (int i = 0; i < 2; i++)
        #pragma unroll
        for (int j = 0; j < 2; j++)
            #pragma unroll
            for (int q = 0; q < 4; q++) acc[i][j][q] = 0.f;

    int xrow = t >> 2, xk8 = (t & 3) * 8;
    int wr = t >> 3, c1 = t & 7;
    uint32_t pbase = smem_u32(xs), wbase = smem_u32(ws);

    int rowM = (lane & 7) + ((lane >> 3) & 1) * 8;
    uint32_t aAddr = pbase + (mi * 32 + rowM) * 80 + (lane >> 4) * 16;
    int cs = (nj * 2 + (lane >> 4)) ^ (lane & 7);
    uint32_t bAddr = wbase + rowM * 128 + cs * 16;

    for (int k0 = 0; k0 < DIN; k0 += 32) {
        __syncthreads();
        {   // X tile 64x32: fp32 -> fp16, stride-80 rows
            float4 x0 = *(const float4*)&X[(size_t)(m0 + xrow) * DIN + k0 + xk8];
            float4 x1 = *(const float4*)&X[(size_t)(m0 + xrow) * DIN + k0 + xk8 + 4];
            __half2 h0 = __floats2half2_rn(x0.x, x0.y);
            __half2 h1 = __floats2half2_rn(x0.z, x0.w);
            __half2 h2 = __floats2half2_rn(x1.x, x1.y);
            __half2 h3 = __floats2half2_rn(x1.z, x1.w);
            uint4 v;
            v.x = *(uint32_t*)&h0; v.y = *(uint32_t*)&h1;
            v.z = *(uint32_t*)&h2; v.w = *(uint32_t*)&h3;
            *(uint4*)&xs[xrow * 80 + (t & 3) * 16] = v;
        }
        {   // W tile 32x64: fp32 -> fp16, 128B rows, chunk swizzle
            float4 w0 = *(const float4*)&W[(size_t)(k0 + wr) * DOUT + n0 + c1 * 8];
            float4 w1 = *(const float4*)&W[(size_t)(k0 + wr) * DOUT + n0 + c1 * 8 + 4];
            __half2 h0 = __floats2half2_rn(w0.x, w0.y);
            __half2 h1 = __floats2half2_rn(w0.z, w0.w);
            __half2 h2 = __floats2half2_rn(w1.x, w1.y);
            __half2 h3 = __floats2half2_rn(w1.z, w1.w);
            uint4 v;
            v.x = *(uint32_t*)&h0; v.y = *(uint32_t*)&h1;
            v.z = *(uint32_t*)&h2; v.w = *(uint32_t*)&h3;
            *(uint4*)&ws[wr * 128 + ((c1 ^ (wr & 7)) * 16)] = v;
        }
        __syncthreads();
        #pragma unroll
        for (int ks = 0; ks < 2; ks++) {
            uint32_t b[4];
            ldmx4t(b, bAddr + ks * 2048);
            #pragma unroll
            for (int itile = 0; itile < 2; itile++) {
                uint32_t a[4];
                ldmx4(a, aAddr + itile * 1280 + ks * 32);
                mma16816(acc[itile][0], a, b[0], b[1]);
                mma16816(acc[itile][1], a, b[2], b[3]);
            }
        }
    }

    #pragma unroll
    for (int itile = 0; itile < 2; itile++) {
        int r0 = m0 + mi * 32 + itile * 16 + (lane >> 2);
        #pragma unroll
        for (int nb = 0; nb < 2; nb++) {
            int c = n0 + nj * 16 + nb * 8 + (lane & 3) * 2;
            __half2 lo = __floats2half2_rn(acc[itile][nb][0], acc[itile][nb][1]);
            __half2 hi = __floats2half2_rn(acc[itile][nb][2], acc[itile][nb][3]);
            *(__half2*)&g_Whh[(size_t)r0 * DOUT + c]       = lo;
            *(__half2*)&g_Whh[(size_t)(r0 + 8) * DOUT + c] = hi;
        }
    }
}

// ---------------- K2: src/dst = X @ wa  (exact fp32 logits) ------------------
__global__ void __launch_bounds__(256) k2_srcdst(const float* __restrict__ X) {
    int lane = threadIdx.x & 31, w = threadIdx.x >> 5;
    int i = blockIdx.x * 8 + w;
    float s1 = 0.f, s2 = 0.f;
    #pragma unroll
    for (int c = lane; c < DIN; c += 32) {
        float x = X[(size_t)i * DIN + c];
        s1 += x * g_wa[0][c];
        s2 += x * g_wa[1][c];
    }
    #pragma unroll
    for (int o = 16; o > 0; o >>= 1) {
        s1 += __shfl_xor_sync(0xffffffffu, s1, o);
        s2 += __shfl_xor_sync(0xffffffffu, s2, o);
    }
    if (lane == 0) { g_src[i] = s1; g_dst[i] = s2; }
}

// ---------------- K2b: dmax = max_j dst[j]  (tiny, one block) ----------------
__global__ void __launch_bounds__(256) k2b_dmax() {
    __shared__ float red[8];
    int t = threadIdx.x;
    float m = -1e30f;
    for (int i = t; i < N_NODES; i += 256) m = fmaxf(m, g_dst[i]);
    #pragma unroll
    for (int o = 16; o > 0; o >>= 1) m = fmaxf(m, __shfl_xor_sync(0xffffffffu, m, o));
    if ((t & 31) == 0) red[t >> 5] = m;
    __syncthreads();
    if (t == 0) {
        float m2 = red[0];
        #pragma unroll
        for (int q = 1; q < 8; q++) m2 = fmaxf(m2, red[q]);
        g_dmax = m2;
    }
}

// ---------------- K4: h' = softmax(P) @ Wh, fused stats, fp16 mma ------------
// R9/R13's proven shape. Grid (2, 128): x = 128-col half, y = 64-row tile.
// Block 256 = 8 warps (mi = w&1 over 32-row halves, nj = w>>1 over 32-col
// quarters). Warp tile 32x32. K-tile 32 = 2 x m16n8k16 steps. P: 64x32 fp16,
// row stride 80B. Wh: 32x128 fp16, 256B rows, chunk swizzle c^(r&7).
// Softmax shift m'_i = leaky(src_i + dmax) >= rowmax (exact-ratio-equivalent);
// row sums accumulated by the builders across all 256 k-tiles (each CTA builds
// the FULL row anyway) -> no separate stats kernel, no extra adj pass.
#define KT   32
#define NIT  (N_NODES / KT)

__global__ void __launch_bounds__(256, 2) k4_attn(const int* __restrict__ adj,
                                                  float* __restrict__ out) {
    __shared__ __align__(16) char whsm[2][8192];   // [stage][32 k-rows][256B]
    __shared__ __align__(16) char psm [2][5120];   // [stage][64 rows][80B]
    __shared__ float src_s[64], linv_s[64];

    int t    = threadIdx.x;
    int lane = t & 31, w = t >> 5;
    int mi = w & 1;          // 32-row half
    int nj = w >> 1;         // 32-col quarter
    int J0 = blockIdx.x * 128;
    int I0 = blockIdx.y * 64;

    if (t < 64) src_s[t] = g_src[I0 + t];

    float acc[2][4][4];
    #pragma unroll
    for (int i = 0; i < 2; i++)
        #pragma unroll
        for (int j = 0; j < 4; j++)
            #pragma unroll
            for (int q = 0; q < 4; q++) acc[i][j][q] = 0.f;

    // ---- builder mapping: row rb = t>>2, k-chunk kc8 = (t&3)*8 ----
    int rb  = t >> 2;
    int kc8 = (t & 3) * 8;
    const int* adjrow = adj + (size_t)(I0 + rb) * N_NODES + kc8;

    // ---- Wh cp.async mapping: row wr = t>>3, chunks c1, c1+8 (swizzled) -----
    int wr = t >> 3, c1 = t & 7;
    uint32_t wh_dst = smem_u32(&whsm[0][0]) + wr * 256 + ((c1 ^ (wr & 7)) * 16);
    const __half* wh_src = &g_Whh[(size_t)wr * DOUT + J0 + c1 * 8];

    // ---- ldmatrix lane address components ----
    uint32_t pbase  = smem_u32(&psm[0][0]);
    uint32_t whbase = smem_u32(&whsm[0][0]);
    int rowM = (lane & 7) + ((lane >> 3) & 1) * 8;       // 0..15
    uint32_t aAddr0 = pbase + (mi * 32 + rowM) * 80 + (lane >> 4) * 16;
    int cs0 = (nj * 4 + 0 + (lane >> 4)) ^ (lane & 7);
    int cs1 = (nj * 4 + 2 + (lane >> 4)) ^ (lane & 7);
    uint32_t bAddr0 = whbase + rowM * 256 + cs0 * 16;
    uint32_t bAddr1 = whbase + rowM * 256 + cs1 * 16;

    // ---- prologue ----
    cp_async16(wh_dst, wh_src);
    cp_async16(wh_dst + 128, wh_src + 64);
    cp_commit();
    int4 aj0 = *(const int4*)&adjrow[0];
    int4 aj1 = *(const int4*)&adjrow[4];

    __syncthreads();    // stats visible
    float sv = src_s[rb];
    float xm = sv + g_dmax;                       // >= src+dst for all j
    float mt2 = fmaxf(xm, ALPHA * xm) * L2E;      // leaky(bound) * log2e
    float psum = 0.f;                             // running row sum (this thread's cols)

    // build P[0]
    {
        float4 d0 = *(const float4*)&g_dst[kc8];
        float4 d1 = *(const float4*)&g_dst[kc8 + 4];
        float xs[8] = {sv + d0.x, sv + d0.y, sv + d0.z, sv + d0.w,
                       sv + d1.x, sv + d1.y, sv + d1.z, sv + d1.w};
        int   am[8] = {aj0.x, aj0.y, aj0.z, aj0.w, aj1.x, aj1.y, aj1.z, aj1.w};
        float p[8];
        #pragma unroll
        for (int c = 0; c < 8; c++) {
            float x = xs[c];
            float e = fmaxf(x, ALPHA * x);
            e = (am[c] > 0) ? e : NEG_INF;
            p[c] = exp2f(fmaf(e, L2E, -mt2));
        }
        psum += ((p[0] + p[1]) + (p[2] + p[3])) + ((p[4] + p[5]) + (p[6] + p[7]));
        __half2 h0 = __floats2half2_rn(p[0], p[1]);
        __half2 h1 = __floats2half2_rn(p[2], p[3]);
        __half2 h2 = __floats2half2_rn(p[4], p[5]);
        __half2 h3 = __floats2half2_rn(p[6], p[7]);
        uint4 v;
        v.x = *(uint32_t*)&h0; v.y = *(uint32_t*)&h1;
        v.z = *(uint32_t*)&h2; v.w = *(uint32_t*)&h3;
        *(uint4*)&psm[0][rb * 80 + (t & 3) * 16] = v;
    }
    // prefetch adj tile 1
    aj0 = *(const int4*)&adjrow[KT];
    aj1 = *(const int4*)&adjrow[KT + 4];

    for (int it = 0; it < NIT; ++it) {
        int cur = it & 1;
        int nxt = cur ^ 1;
        bool more = (it + 1 < NIT);

        cp_wait<0>();
        __syncthreads();   // publishes stage cur; retires all reads of nxt

        if (more) {
            int kn = (it + 1) * KT;
            // Wh[nxt]
            cp_async16(wh_dst + nxt * 8192, wh_src + (size_t)kn * DOUT);
            cp_async16(wh_dst + nxt * 8192 + 128, wh_src + (size_t)kn * DOUT + 64);
            cp_commit();

            // build P[nxt] (tile it+1)
            {
                float4 d0 = *(const float4*)&g_dst[kn + kc8];
                float4 d1 = *(const float4*)&g_dst[kn + kc8 + 4];
                float xs[8] = {sv + d0.x, sv + d0.y, sv + d0.z, sv + d0.w,
                               sv + d1.x, sv + d1.y, sv + d1.z, sv + d1.w};
                int   am[8] = {aj0.x, aj0.y, aj0.z, aj0.w,
                               aj1.x, aj1.y, aj1.z, aj1.w};
                float p[8];
                #pragma unroll
                for (int c = 0; c < 8; c++) {
                    float x = xs[c];
                    float e = fmaxf(x, ALPHA * x);
                    e = (am[c] > 0) ? e : NEG_INF;
                    p[c] = exp2f(fmaf(e, L2E, -mt2));
                }
                psum += ((p[0] + p[1]) + (p[2] + p[3]))
                      + ((p[4] + p[5]) + (p[6] + p[7]));
                __half2 h0 = __floats2half2_rn(p[0], p[1]);
                __half2 h1 = __floats2half2_rn(p[2], p[3]);
                __half2 h2 = __floats2half2_rn(p[4], p[5]);
                __half2 h3 = __floats2half2_rn(p[6], p[7]);
                uint4 v;
                v.x = *(uint32_t*)&h0; v.y = *(uint32_t*)&h1;
                v.z = *(uint32_t*)&h2; v.w = *(uint32_t*)&h3;
                *(uint4*)&psm[nxt][rb * 80 + (t & 3) * 16] = v;
            }

            // prefetch adj for tile it+2
            if (it + 2 < NIT) {
                const int* ab = adjrow + (it + 2) * KT;
                aj0 = *(const int4*)&ab[0];
                aj1 = *(const int4*)&ab[4];
            }
        }

        // ---- MMA on stage cur: warp tile 32 rows x 32 cols ----
        {
            uint32_t aA = aAddr0 + cur * 5120;
            uint32_t bA0 = bAddr0 + cur * 8192;
            uint32_t bA1 = bAddr1 + cur * 8192;
            #pragma unroll
            for (int ks = 0; ks < 2; ks++) {
                uint32_t b0[4], b1[4];
                ldmx4t(b0, bA0 + ks * 4096);   // cols nj*32+0..15, k 16
                ldmx4t(b1, bA1 + ks * 4096);   // cols nj*32+16..31
                #pragma unroll
                for (int itile = 0; itile < 2; itile++) {
                    uint32_t a[4];
                    ldmx4(a, aA + itile * 1280 + ks * 32);
                    mma16816(acc[itile][0], a, b0[0], b0[1]);
                    mma16816(acc[itile][1], a, b0[2], b0[3]);
                    mma16816(acc[itile][2], a, b1[0], b1[1]);
                    mma16816(acc[itile][3], a, b1[2], b1[3]);
                }
            }
        }
    }

    // ---- finalize row sums: reduce the 4 builder threads per row ----
    psum += __shfl_xor_sync(0xffffffffu, psum, 1);
    psum += __shfl_xor_sync(0xffffffffu, psum, 2);
    if ((t & 3) == 0) linv_s[rb] = 1.0f / psum;
    __syncthreads();

    // ---- epilogue: /rowsum, ELU, store ----
    #pragma unroll
    for (int itile = 0; itile < 2; itile++) {
        int r0 = mi * 32 + itile * 16 + (lane >> 2);
        float l0 = linv_s[r0], l1 = linv_s[r0 + 8];
        #pragma unroll
        for (int nb = 0; nb < 4; nb++) {
            int c = J0 + nj * 32 + nb * 8 + (lane & 3) * 2;
            float v0 = acc[itile][nb][0] * l0;
            float v1 = acc[itile][nb][1] * l0;
            float v2 = acc[itile][nb][2] * l1;
            float v3 = acc[itile][nb][3] * l1;
            float2 lo, hi;
            lo.x = (v0 > 0.f) ? v0 : expm1f(v0);
            lo.y = (v1 > 0.f) ? v1 : expm1f(v1);
            hi.x = (v2 > 0.f) ? v2 : expm1f(v2);
            hi.y = (v3 > 0.f) ? v3 : expm1f(v3);
            *(float2*)&out[(size_t)(I0 + r0)     * DOUT + c] = lo;
            *(float2*)&out[(size_t)(I0 + r0 + 8) * DOUT + c] = hi;
        }
    }
}

// ---------------- launch ------------------------------------------------------
extern "C" void kernel_launch(void* const* d_in, const int* in_sizes, int n_in,
                              void* d_out, int out_size) {
    const float* X   = (const float*)d_in[0];   // features [8192,512]
    const int*   adj = (const int*)  d_in[1];   // adj      [8192,8192]
    const float* W   = (const float*)d_in[2];   // W        [512,256]
    const float* a   = (const float*)d_in[3];   // a        [512,1]
    float* out = (float*)d_out;                 // [8192,256]

    k0_wa     <<<128, 256>>>(W, a);
    k2_srcdst <<<N_NODES / 8, 256>>>(X);
    k2b_dmax  <<<1, 256>>>();
    k1_gemm   <<<dim3(N_NODES / 64, DOUT / 64), 256>>>(X, W);
    k4_attn   <<<dim3(DOUT / 128, N_NODES / 64), 256>>>(adj, out);
}

// round 15
// speedup vs baseline: 1.7914x; 1.0337x over previous
#include <cuda_runtime.h>
#include <cuda_fp16.h>
#include <cstdint>
#include <cstddef>

#define N_NODES 8192
#define DIN     512
#define DOUT    256
#define ALPHA   0.2f
#define NEG_INF -9e15f
#define L2E     1.4426950408889634f

// ---------------- scratch (device globals; no allocations allowed) ----------
__device__ __half g_Whh[(size_t)N_NODES * DOUT];   // 4 MB fp16 row-major (k4 B)
__device__ float  g_wa[2][DIN];                    // W @ a halves (k0 -> k2)
__device__ float g_src[N_NODES];
__device__ float g_dst[N_NODES];
__device__ float g_dmax;                           // max_j dst[j]

// ---------------- helpers ----------------------------------------------------
__device__ __forceinline__ uint32_t smem_u32(const void* p) {
    uint32_t a;
    asm("{ .reg .u64 t; cvta.to.shared.u64 t, %1; cvt.u32.u64 %0, t; }"
        : "=r"(a) : "l"(p));
    return a;
}
__device__ __forceinline__ void ldmx4(uint32_t* r, uint32_t addr) {
    asm volatile("ldmatrix.sync.aligned.m8n8.x4.shared.b16 {%0,%1,%2,%3}, [%4];"
                 : "=r"(r[0]), "=r"(r[1]), "=r"(r[2]), "=r"(r[3]) : "r"(addr));
}
__device__ __forceinline__ void ldmx4t(uint32_t* r, uint32_t addr) {
    asm volatile("ldmatrix.sync.aligned.m8n8.x4.trans.shared.b16 {%0,%1,%2,%3}, [%4];"
                 : "=r"(r[0]), "=r"(r[1]), "=r"(r[2]), "=r"(r[3]) : "r"(addr));
}
__device__ __forceinline__ void mma16816(float* c, const uint32_t* a,
                                         uint32_t b0, uint32_t b1) {
    asm volatile(
        "mma.sync.aligned.m16n8k16.row.col.f32.f16.f16.f32 "
        "{%0,%1,%2,%3}, {%4,%5,%6,%7}, {%8,%9}, {%0,%1,%2,%3};\n"
        : "+f"(c[0]), "+f"(c[1]), "+f"(c[2]), "+f"(c[3])
        : "r"(a[0]), "r"(a[1]), "r"(a[2]), "r"(a[3]), "r"(b0), "r"(b1));
}
__device__ __forceinline__ void cp_async16(uint32_t smem_addr, const void* gptr) {
    asm volatile("cp.async.cg.shared.global [%0], [%1], 16;\n"
                 :: "r"(smem_addr), "l"(gptr));
}
__device__ __forceinline__ void cp_commit() {
    asm volatile("cp.async.commit_group;\n" ::: "memory");
}
template <int N>
__device__ __forceinline__ void cp_wait() {
    asm volatile("cp.async.wait_group %0;\n" :: "n"(N) : "memory");
}

// ---------------- K0: wa[p][k] = sum_d W[k][d] * a[p*256+d]  (tiny) ----------
__global__ void __launch_bounds__(256) k0_wa(const float* __restrict__ W,
                                             const float* __restrict__ a) {
    int lane = threadIdx.x & 31, w = threadIdx.x >> 5;
    int id = blockIdx.x * 8 + w;          // 0..1023
    int proj = id >> 9, k = id & 511;
    float s = 0.f;
    #pragma unroll
    for (int d = lane; d < DOUT; d += 32)
        s += W[(size_t)k * DOUT + d] * a[proj * DOUT + d];
    #pragma unroll
    for (int o = 16; o > 0; o >>= 1) s += __shfl_xor_sync(0xffffffffu, s, o);
    if (lane == 0) g_wa[proj][k] = s;
}

// ---------------- K1: Whh = fp16( X @ W )  via ldmatrix + HMMA ---------------
__global__ void __launch_bounds__(256) k1_gemm(const float* __restrict__ X,
                                               const float* __restrict__ W) {
    __shared__ __align__(16) char xs[5120];   // 64 rows x 80B (fp16, stride 80)
    __shared__ __align__(16) char ws[4096];   // 32 k-rows x 128B, swizzle c^(r&7)
    int t    = threadIdx.x;
    int lane = t & 31, w = t >> 5;
    int mi = w & 1, nj = w >> 1;
    int m0 = blockIdx.x * 64, n0 = blockIdx.y * 64;

    float acc[2][2][4];
    #pragma unroll
    for (int i = 0; i < 2; i++)
        #pragma unroll
        for (int j = 0; j < 2; j++)
            #pragma unroll
            for (int q = 0; q < 4; q++) acc[i][j][q] = 0.f;

    int xrow = t >> 2, xk8 = (t & 3) * 8;
    int wr = t >> 3, c1 = t & 7;
    uint32_t pbase = smem_u32(xs), wbase = smem_u32(ws);

    int rowM = (lane & 7) + ((lane >> 3) & 1) * 8;
    uint32_t aAddr = pbase + (mi * 32 + rowM) * 80 + (lane >> 4) * 16;
    int cs = (nj * 2 + (lane >> 4)) ^ (lane & 7);
    uint32_t bAddr = wbase + rowM * 128 + cs * 16;

    for (int k0 = 0; k0 < DIN; k0 += 32) {
        __syncthreads();
        {   // X tile 64x32: fp32 -> fp16, stride-80 rows
            float4 x0 = *(const float4*)&X[(size_t)(m0 + xrow) * DIN + k0 + xk8];
            float4 x1 = *(const float4*)&X[(size_t)(m0 + xrow) * DIN + k0 + xk8 + 4];
            __half2 h0 = __floats2half2_rn(x0.x, x0.y);
            __half2 h1 = __floats2half2_rn(x0.z, x0.w);
            __half2 h2 = __floats2half2_rn(x1.x, x1.y);
            __half2 h3 = __floats2half2_rn(x1.z, x1.w);
            uint4 v;
            v.x = *(uint32_t*)&h0; v.y = *(uint32_t*)&h1;
            v.z = *(uint32_t*)&h2; v.w = *(uint32_t*)&h3;
            *(uint4*)&xs[xrow * 80 + (t & 3) * 16] = v;
        }
        {   // W tile 32x64: fp32 -> fp16, 128B rows, chunk swizzle
            float4 w0 = *(const float4*)&W[(size_t)(k0 + wr) * DOUT + n0 + c1 * 8];
            float4 w1 = *(const float4*)&W[(size_t)(k0 + wr) * DOUT + n0 + c1 * 8 + 4];
            __half2 h0 = __floats2half2_rn(w0.x, w0.y);
            __half2 h1 = __floats2half2_rn(w0.z, w0.w);
            __half2 h2 = __floats2half2_rn(w1.x, w1.y);
            __half2 h3 = __floats2half2_rn(w1.z, w1.w);
            uint4 v;
            v.x = *(uint32_t*)&h0; v.y = *(uint32_t*)&h1;
            v.z = *(uint32_t*)&h2; v.w = *(uint32_t*)&h3;
            *(uint4*)&ws[wr * 128 + ((c1 ^ (wr & 7)) * 16)] = v;
        }
        __syncthreads();
        #pragma unroll
        for (int ks = 0; ks < 2; ks++) {
            uint32_t b[4];
            ldmx4t(b, bAddr + ks * 2048);
            #pragma unroll
            for (int itile = 0; itile < 2; itile++) {
                uint32_t a[4];
                ldmx4(a, aAddr + itile * 1280 + ks * 32);
                mma16816(acc[itile][0], a, b[0], b[1]);
                mma16816(acc[itile][1], a, b[2], b[3]);
            }
        }
    }

    #pragma unroll
    for (int itile = 0; itile < 2; itile++) {
        int r0 = m0 + mi * 32 + itile * 16 + (lane >> 2);
        #pragma unroll
        for (int nb = 0; nb < 2; nb++) {
            int c = n0 + nj * 16 + nb * 8 + (lane & 3) * 2;
            __half2 lo = __floats2half2_rn(acc[itile][nb][0], acc[itile][nb][1]);
            __half2 hi = __floats2half2_rn(acc[itile][nb][2], acc[itile][nb][3]);
            *(__half2*)&g_Whh[(size_t)r0 * DOUT + c]       = lo;
            *(__half2*)&g_Whh[(size_t)(r0 + 8) * DOUT + c] = hi;
        }
    }
}

// ---------------- K2: src/dst = X @ wa  (exact fp32 logits) ------------------
__global__ void __launch_bounds__(256) k2_srcdst(const float* __restrict__ X) {
    int lane = threadIdx.x & 31, w = threadIdx.x >> 5;
    int i = blockIdx.x * 8 + w;
    float s1 = 0.f, s2 = 0.f;
    #pragma unroll
    for (int c = lane; c < DIN; c += 32) {
        float x = X[(size_t)i * DIN + c];
        s1 += x * g_wa[0][c];
        s2 += x * g_wa[1][c];
    }
    #pragma unroll
    for (int o = 16; o > 0; o >>= 1) {
        s1 += __shfl_xor_sync(0xffffffffu, s1, o);
        s2 += __shfl_xor_sync(0xffffffffu, s2, o);
    }
    if (lane == 0) { g_src[i] = s1; g_dst[i] = s2; }
}

// ---------------- K2b: dmax = max_j dst[j]  (tiny, one block) ----------------
__global__ void __launch_bounds__(256) k2b_dmax() {
    __shared__ float red[8];
    int t = threadIdx.x;
    float m = -1e30f;
    for (int i = t; i < N_NODES; i += 256) m = fmaxf(m, g_dst[i]);
    #pragma unroll
    for (int o = 16; o > 0; o >>= 1) m = fmaxf(m, __shfl_xor_sync(0xffffffffu, m, o));
    if ((t & 31) == 0) red[t >> 5] = m;
    __syncthreads();
    if (t == 0) {
        float m2 = red[0];
        #pragma unroll
        for (int q = 1; q < 8; q++) m2 = fmaxf(m2, red[q]);
        g_dmax = m2;
    }
}

// ---------------- K4: h' = softmax(P) @ Wh, fused stats, KT=64 ---------------
// Grid (2, 128): x = 128-col half, y = 64-row tile. Block 256 = 8 warps
// (mi = w&1 over 32-row halves, nj = w>>1 over 32-col quarters). Warp tile
// 32x32, K-tile 64 = 4 x m16n8k16 steps (128 iterations, half the barriers).
// P: 64x64 fp16, row stride 144B (bank-clean). Wh: 64 k-rows x 256B, chunk
// swizzle c^(r&7). Double-buffered, one barrier per tile. Softmax shift
// m'_i = leaky(src_i + dmax); row sums fused into the builders.
#define KT        64
#define NIT       (N_NODES / KT)
#define WH_STAGE  16384
#define P_STAGE   9216
#define P_OFF     (2 * WH_STAGE)               // 32768
#define STAT_OFF  (P_OFF + 2 * P_STAGE)        // 51200
#define SMEM_K4   (STAT_OFF + 512)             // 51712

__global__ void __launch_bounds__(256, 2) k4_attn(const int* __restrict__ adj,
                                                  float* __restrict__ out) {
    extern __shared__ __align__(16) char smem[];
    float* src_s  = (float*)(smem + STAT_OFF);
    float* linv_s = src_s + 64;

    int t    = threadIdx.x;
    int lane = t & 31, w = t >> 5;
    int mi = w & 1;          // 32-row half
    int nj = w >> 1;         // 32-col quarter
    int J0 = blockIdx.x * 128;
    int I0 = blockIdx.y * 64;

    if (t < 64) src_s[t] = g_src[I0 + t];

    float acc[2][4][4];
    #pragma unroll
    for (int i = 0; i < 2; i++)
        #pragma unroll
        for (int j = 0; j < 4; j++)
            #pragma unroll
            for (int q = 0; q < 4; q++) acc[i][j][q] = 0.f;

    // ---- builder mapping: row rb = t>>2, cols kc16 = (t&3)*16 ----
    int rb   = t >> 2;
    int kc16 = (t & 3) * 16;
    const int* adjrow = adj + (size_t)(I0 + rb) * N_NODES + kc16;

    // ---- Wh cp.async mapping: row wr = t>>2, 4 chunks (t&3)*4+q (swizzled) --
    int wr = t >> 2;
    uint32_t whbase = smem_u32(smem);
    uint32_t pbase  = smem_u32(smem + P_OFF);
    uint32_t wh_dst_row = whbase + wr * 256;
    int      wcb        = (t & 3) * 4;
    const __half* wh_src_row = &g_Whh[(size_t)wr * DOUT + J0];

    // ---- ldmatrix lane address components ----
    int rowM = (lane & 7) + ((lane >> 3) & 1) * 8;       // 0..15
    uint32_t aAddr0 = pbase + (mi * 32 + rowM) * 144 + (lane >> 4) * 16;
    int cs0 = (nj * 4 + 0 + (lane >> 4)) ^ (lane & 7);
    int cs1 = (nj * 4 + 2 + (lane >> 4)) ^ (lane & 7);
    uint32_t bAddr0 = whbase + rowM * 256 + cs0 * 16;
    uint32_t bAddr1 = whbase + rowM * 256 + cs1 * 16;

    // ---- prologue: Wh[0] cp.async + adj tile 0 regs ----
    #pragma unroll
    for (int q = 0; q < 4; q++) {
        int c = wcb + q;
        cp_async16(wh_dst_row + ((c ^ (wr & 7)) * 16), wh_src_row + c * 8);
    }
    cp_commit();
    int4 ajr[4];
    #pragma unroll
    for (int q = 0; q < 4; q++) ajr[q] = *(const int4*)&adjrow[q * 4];

    __syncthreads();    // src_s visible
    float sv = src_s[rb];
    float xm = sv + g_dmax;                       // >= src+dst for all j
    float mt2 = fmaxf(xm, ALPHA * xm) * L2E;      // leaky(bound) * log2e
    float psum = 0.f;

    // build P[0]
    {
        float p[16];
        #pragma unroll
        for (int q = 0; q < 4; q++) {
            float4 dv = *(const float4*)&g_dst[kc16 + q * 4];
            float xs[4] = {sv + dv.x, sv + dv.y, sv + dv.z, sv + dv.w};
            int   am[4] = {ajr[q].x, ajr[q].y, ajr[q].z, ajr[q].w};
            #pragma unroll
            for (int c = 0; c < 4; c++) {
                float x = xs[c];
                float e = fmaxf(x, ALPHA * x);
                e = (am[c] > 0) ? e : NEG_INF;
                p[q * 4 + c] = exp2f(fmaf(e, L2E, -mt2));
            }
        }
        #pragma unroll
        for (int q = 0; q < 16; q++) psum += p[q];
        uint32_t pd = pbase + rb * 144 + (t & 3) * 32;
        uint4 v0, v1;
        __half2 h;
        h = __floats2half2_rn(p[0],  p[1]);  v0.x = *(uint32_t*)&h;
        h = __floats2half2_rn(p[2],  p[3]);  v0.y = *(uint32_t*)&h;
        h = __floats2half2_rn(p[4],  p[5]);  v0.z = *(uint32_t*)&h;
        h = __floats2half2_rn(p[6],  p[7]);  v0.w = *(uint32_t*)&h;
        h = __floats2half2_rn(p[8],  p[9]);  v1.x = *(uint32_t*)&h;
        h = __floats2half2_rn(p[10], p[11]); v1.y = *(uint32_t*)&h;
        h = __floats2half2_rn(p[12], p[13]); v1.z = *(uint32_t*)&h;
        h = __floats2half2_rn(p[14], p[15]); v1.w = *(uint32_t*)&h;
        asm volatile("st.shared.v4.b32 [%0], {%1,%2,%3,%4};" ::
                     "r"(pd), "r"(v0.x), "r"(v0.y), "r"(v0.z), "r"(v0.w));
        asm volatile("st.shared.v4.b32 [%0], {%1,%2,%3,%4};" ::
                     "r"(pd + 16), "r"(v1.x), "r"(v1.y), "r"(v1.z), "r"(v1.w));
    }
    // prefetch adj tile 1
    #pragma unroll
    for (int q = 0; q < 4; q++) ajr[q] = *(const int4*)&adjrow[KT + q * 4];

    for (int it = 0; it < NIT; ++it) {
        int cur = it & 1;
        int nxt = cur ^ 1;
        bool more = (it + 1 < NIT);

        cp_wait<0>();
        __syncthreads();   // publishes stage cur; retires all reads of nxt

        if (more) {
            int kn = (it + 1) * KT;
            // Wh[nxt]
            #pragma unroll
            for (int q = 0; q < 4; q++) {
                int c = wcb + q;
                cp_async16(wh_dst_row + nxt * WH_STAGE + ((c ^ (wr & 7)) * 16),
                           wh_src_row + (size_t)kn * DOUT + c * 8);
            }
            cp_commit();

            // build P[nxt] (tile it+1)
            {
                float p[16];
                #pragma unroll
                for (int q = 0; q < 4; q++) {
                    float4 dv = *(const float4*)&g_dst[kn + kc16 + q * 4];
                    float xs[4] = {sv + dv.x, sv + dv.y, sv + dv.z, sv + dv.w};
                    int   am[4] = {ajr[q].x, ajr[q].y, ajr[q].z, ajr[q].w};
                    #pragma unroll
                    for (int c = 0; c < 4; c++) {
                        float x = xs[c];
                        float e = fmaxf(x, ALPHA * x);
                        e = (am[c] > 0) ? e : NEG_INF;
                        p[q * 4 + c] = exp2f(fmaf(e, L2E, -mt2));
                    }
                }
                #pragma unroll
                for (int q = 0; q < 16; q++) psum += p[q];
                uint32_t pd = pbase + nxt * P_STAGE + rb * 144 + (t & 3) * 32;
                uint4 v0, v1;
                __half2 h;
                h = __floats2half2_rn(p[0],  p[1]);  v0.x = *(uint32_t*)&h;
                h = __floats2half2_rn(p[2],  p[3]);  v0.y = *(uint32_t*)&h;
                h = __floats2half2_rn(p[4],  p[5]);  v0.z = *(uint32_t*)&h;
                h = __floats2half2_rn(p[6],  p[7]);  v0.w = *(uint32_t*)&h;
                h = __floats2half2_rn(p[8],  p[9]);  v1.x = *(uint32_t*)&h;
                h = __floats2half2_rn(p[10], p[11]); v1.y = *(uint32_t*)&h;
                h = __floats2half2_rn(p[12], p[13]); v1.z = *(uint32_t*)&h;
                h = __floats2half2_rn(p[14], p[15]); v1.w = *(uint32_t*)&h;
                asm volatile("st.shared.v4.b32 [%0], {%1,%2,%3,%4};" ::
                             "r"(pd), "r"(v0.x), "r"(v0.y), "r"(v0.z), "r"(v0.w));
                asm volatile("st.shared.v4.b32 [%0], {%1,%2,%3,%4};" ::
                             "r"(pd + 16), "r"(v1.x), "r"(v1.y), "r"(v1.z), "r"(v1.w));
            }

            // prefetch adj for tile it+2
            if (it + 2 < NIT) {
                const int* ab = adjrow + (it + 2) * KT;
                #pragma unroll
                for (int q = 0; q < 4; q++) ajr[q] = *(const int4*)&ab[q * 4];
            }
        }

        // ---- MMA on stage cur: warp tile 32 rows x 32 cols, 4 k-steps ----
        {
            uint32_t aA  = aAddr0 + cur * P_STAGE;
            uint32_t bA0 = bAddr0 + cur * WH_STAGE;
            uint32_t bA1 = bAddr1 + cur * WH_STAGE;
            #pragma unroll
            for (int ks = 0; ks < 4; ks++) {
                uint32_t b0[4], b1[4];
                ldmx4t(b0, bA0 + ks * 4096);   // cols nj*32+0..15, k-rows ks*16..+15
                ldmx4t(b1, bA1 + ks * 4096);   // cols nj*32+16..31
                #pragma unroll
                for (int itile = 0; itile < 2; itile++) {
                    uint32_t a[4];
                    ldmx4(a, aA + itile * 2304 + ks * 32);
                    mma16816(acc[itile][0], a, b0[0], b0[1]);
                    mma16816(acc[itile][1], a, b0[2], b0[3]);
                    mma16816(acc[itile][2], a, b1[0], b1[1]);
                    mma16816(acc[itile][3], a, b1[2], b1[3]);
                }
            }
        }
    }

    // ---- finalize row sums: reduce the 4 builder threads per row ----
    psum += __shfl_xor_sync(0xffffffffu, psum, 1);
    psum += __shfl_xor_sync(0xffffffffu, psum, 2);
    if ((t & 3) == 0) linv_s[rb] = 1.0f / psum;
    __syncthreads();

    // ---- epilogue: /rowsum, ELU, store ----
    #pragma unroll
    for (int itile = 0; itile < 2; itile++) {
        int r0 = mi * 32 + itile * 16 + (lane >> 2);
        float l0 = linv_s[r0], l1 = linv_s[r0 + 8];
        #pragma unroll
        for (int nb = 0; nb < 4; nb++) {
            int c = J0 + nj * 32 + nb * 8 + (lane & 3) * 2;
            float v0 = acc[itile][nb][0] * l0;
            float v1 = acc[itile][nb][1] * l0;
            float v2 = acc[itile][nb][2] * l1;
            float v3 = acc[itile][nb][3] * l1;
            float2 lo, hi;
            lo.x = (v0 > 0.f) ? v0 : expm1f(v0);
            lo.y = (v1 > 0.f) ? v1 : expm1f(v1);
            hi.x = (v2 > 0.f) ? v2 : expm1f(v2);
            hi.y = (v3 > 0.f) ? v3 : expm1f(v3);
            *(float2*)&out[(size_t)(I0 + r0)     * DOUT + c] = lo;
            *(float2*)&out[(size_t)(I0 + r0 + 8) * DOUT + c] = hi;
        }
    }
}

// ---------------- launch ------------------------------------------------------
extern "C" void kernel_launch(void* const* d_in, const int* in_sizes, int n_in,
                              void* d_out, int out_size) {
    const float* X   = (const float*)d_in[0];   // features [8192,512]
    const int*   adj = (const int*)  d_in[1];   // adj      [8192,8192]
    const float* W   = (const float*)d_in[2];   // W        [512,256]
    const float* a   = (const float*)d_in[3];   // a        [512,1]
    float* out = (float*)d_out;                 // [8192,256]

    static bool attr_done = false;
    if (!attr_done) {
        cudaFuncSetAttribute(k4_attn, cudaFuncAttributeMaxDynamicSharedMemorySize,
                             SMEM_K4);
        attr_done = true;
    }

    k0_wa     <<<128, 256>>>(W, a);
    k2_srcdst <<<N_NODES / 8, 256>>>(X);
    k2b_dmax  <<<1, 256>>>();
    k1_gemm   <<<dim3(N_NODES / 64, DOUT / 64), 256>>>(X, W);
    k4_attn   <<<dim3(DOUT / 128, N_NODES / 64), 256, SMEM_K4>>>(adj, out);
}